// round 1
// baseline (speedup 1.0000x reference)
#include <cuda_runtime.h>

#define B_    4
#define CIN_  128
#define COUT_ 256
#define EMAX_ 20000
#define EPSBN 1e-5f

// Scratch (module-allocated __device__ globals: no cudaMalloc)
__device__ float g_xt[(size_t)B_ * EMAX_ * CIN_];    // x transposed: [b][e][c]
__device__ float g_yt[(size_t)B_ * EMAX_ * COUT_];   // conv0 output transposed: [b][e][o]
__device__ float g_sum[COUT_];
__device__ float g_sumsq[COUT_];
__device__ float g_a[COUT_];
__device__ float g_bsh[COUT_];

// ---------------------------------------------------------------------------
// Transpose x [B][CIN][E] -> g_xt [B][E][CIN]
// ---------------------------------------------------------------------------
__global__ void transpose_k(const float* __restrict__ x, int E) {
    __shared__ float tile[32][33];
    int b  = blockIdx.z;
    int c0 = blockIdx.y * 32;
    int e0 = blockIdx.x * 32;
    for (int r = threadIdx.y; r < 32; r += 8) {
        int c = c0 + r;
        int e = e0 + threadIdx.x;
        float v = (e < E) ? x[((size_t)b * CIN_ + c) * E + e] : 0.f;
        tile[r][threadIdx.x] = v;
    }
    __syncthreads();
    for (int r = threadIdx.y; r < 32; r += 8) {
        int e = e0 + r;
        int c = c0 + threadIdx.x;
        if (e < E) g_xt[((size_t)b * E + e) * CIN_ + c] = tile[threadIdx.x][r];
    }
}

// ---------------------------------------------------------------------------
// Fused gather + symmetric-function + GEMM.
//   PHASE2=false: src=g_xt, out=g_yt (transposed store)
//   PHASE2=true : src=g_yt with z = a_c*relu(v)+b_c applied in the gather,
//                 out = d_out with residual (+yt) and relu.
// Block tile: 128 (out ch) x 128 (edges), K chunk = 16 ch * 5 = 80.
// ---------------------------------------------------------------------------
template <int CIN, bool PHASE2>
__global__ __launch_bounds__(256) void conv_k(const int* __restrict__ gmm,
                                              const float* __restrict__ w,
                                              float* __restrict__ dout, int E) {
    constexpr int KC = 16;          // channels per K chunk
    constexpr int KB = KC * 5;      // 80 K values per chunk
    constexpr int BM = 128;         // output channels per block
    constexpr int BN = 128;         // edges per block
    constexpr int GP = 132;         // padded G row (bank-conflict relief)

    extern __shared__ float smem[];
    float* Ws   = smem;                         // [BM][KB] row-major (as global w)
    float* Gs   = smem + BM * KB;               // [KB][GP]
    int*   idxs = (int*)(smem + BM * KB + KB * GP);  // [4][BN]

    const float* src  = PHASE2 ? g_yt : g_xt;
    float*       outp = PHASE2 ? dout : g_yt;

    int tid = threadIdx.x;
    int tx = tid & 15;
    int ty = tid >> 4;
    int e0 = blockIdx.x * BN;
    int o0 = blockIdx.y * BM;
    int b  = blockIdx.z;
    const float* srcb = src + (size_t)b * E * CIN;

    // Neighbor indices for this edge tile
    for (int i = tid; i < 4 * BN; i += 256) {
        int el = i >> 2, j = i & 3;
        int eg = e0 + el;
        idxs[j * BN + el] = (eg < E) ? gmm[((size_t)b * E + eg) * 4 + j] : 0;
    }

    float acc[8][8];
#pragma unroll
    for (int u = 0; u < 8; u++)
#pragma unroll
        for (int j = 0; j < 8; j++) acc[u][j] = 0.f;

    const int nch = CIN / KC;
    for (int cc = 0; cc < nch; cc++) {
        int c0 = cc * KC;
        __syncthreads();

        // ---- stage weight chunk: Ws[o][k] = w[o0+o][c0*5 + k], 20 float4 per row
        for (int i = tid; i < BM * (KB / 4); i += 256) {
            int o = i / (KB / 4), kq = i % (KB / 4);
            float4 v = *(const float4*)(w + ((size_t)(o0 + o) * CIN + c0) * 5 + kq * 4);
            *(float4*)(Ws + o * KB + kq * 4) = v;
        }

        // ---- stage G chunk: gather 5 rows per edge, symmetric funcs
        {
            int ch = tid & (KC - 1);
            int elb = tid >> 4;
            int c = c0 + ch;
            float ac = 0.f, bc = 0.f;
            if constexpr (PHASE2) { ac = g_a[c]; bc = g_bsh[c]; }
#pragma unroll 1
            for (int p = 0; p < BN / 16; p++) {
                int el = elb + p * 16;
                int eg = e0 + el;
                int si = (eg < E) ? eg : 0;
                int g1 = idxs[0 * BN + el];
                int g2 = idxs[1 * BN + el];
                int g3 = idxs[2 * BN + el];
                int g4 = idxs[3 * BN + el];
                float v0 = srcb[(size_t)si * CIN + c];
                float v1 = srcb[(size_t)g1 * CIN + c];
                float v2 = srcb[(size_t)g2 * CIN + c];
                float v3 = srcb[(size_t)g3 * CIN + c];
                float v4 = srcb[(size_t)g4 * CIN + c];
                if constexpr (PHASE2) {
                    v0 = fmaf(ac, fmaxf(v0, 0.f), bc);
                    v1 = fmaf(ac, fmaxf(v1, 0.f), bc);
                    v2 = fmaf(ac, fmaxf(v2, 0.f), bc);
                    v3 = fmaf(ac, fmaxf(v3, 0.f), bc);
                    v4 = fmaf(ac, fmaxf(v4, 0.f), bc);
                }
                float* gp = Gs + (ch * 5) * GP + el;
                gp[0 * GP] = v0;
                gp[1 * GP] = v1 + v3;
                gp[2 * GP] = v2 + v4;
                gp[3 * GP] = fabsf(v1 - v3);
                gp[4 * GP] = fabsf(v2 - v4);
            }
        }
        __syncthreads();

        // ---- compute: 8x8 register tile per thread, k unrolled by 4
#pragma unroll 2
        for (int kq = 0; kq < KB / 4; kq++) {
            float br[4][8];
#pragma unroll
            for (int kk = 0; kk < 4; kk++) {
                int k = kq * 4 + kk;
                float4 t0 = *(const float4*)(Gs + k * GP + tx * 4);
                float4 t1 = *(const float4*)(Gs + k * GP + tx * 4 + 64);
                br[kk][0] = t0.x; br[kk][1] = t0.y; br[kk][2] = t0.z; br[kk][3] = t0.w;
                br[kk][4] = t1.x; br[kk][5] = t1.y; br[kk][6] = t1.z; br[kk][7] = t1.w;
            }
#pragma unroll
            for (int u = 0; u < 8; u++) {
                int ol = ty * 4 + (u & 3) + (u >> 2) * 64;
                float4 av = *(const float4*)(Ws + ol * KB + kq * 4);
                float ar[4] = {av.x, av.y, av.z, av.w};
#pragma unroll
                for (int kk = 0; kk < 4; kk++)
#pragma unroll
                    for (int j = 0; j < 8; j++)
                        acc[u][j] = fmaf(ar[kk], br[kk][j], acc[u][j]);
            }
        }
    }

    // ---- epilogue
    if constexpr (!PHASE2) {
        // store transposed: yt[b][e][o]
#pragma unroll
        for (int j = 0; j < 8; j++) {
            int e = e0 + tx * 4 + (j & 3) + (j >> 2) * 64;
            if (e >= E) continue;
            float* yrow = g_yt + ((size_t)b * E + e) * COUT_ + o0 + ty * 4;
            *(float4*)(yrow)      = make_float4(acc[0][j], acc[1][j], acc[2][j], acc[3][j]);
            *(float4*)(yrow + 64) = make_float4(acc[4][j], acc[5][j], acc[6][j], acc[7][j]);
        }
    } else {
        // residual add from yt (same access pattern as conv0 store)
#pragma unroll
        for (int j = 0; j < 8; j++) {
            int e = e0 + tx * 4 + (j & 3) + (j >> 2) * 64;
            if (e >= E) continue;
            const float* yrow = g_yt + ((size_t)b * E + e) * COUT_ + o0 + ty * 4;
            float4 r0 = *(const float4*)(yrow);
            float4 r1 = *(const float4*)(yrow + 64);
            acc[0][j] += r0.x; acc[1][j] += r0.y; acc[2][j] += r0.z; acc[3][j] += r0.w;
            acc[4][j] += r1.x; acc[5][j] += r1.y; acc[6][j] += r1.z; acc[7][j] += r1.w;
        }
        // relu + store [b][o][e], coalesced float4 along e
#pragma unroll
        for (int u = 0; u < 8; u++) {
            int o = o0 + ty * 4 + (u & 3) + (u >> 2) * 64;
            float* orow = outp + ((size_t)b * COUT_ + o) * E;
#pragma unroll
            for (int jg = 0; jg < 2; jg++) {
                int e = e0 + tx * 4 + jg * 64;
                if (e + 3 < E) {
                    float4 v = make_float4(fmaxf(acc[u][jg * 4 + 0], 0.f),
                                           fmaxf(acc[u][jg * 4 + 1], 0.f),
                                           fmaxf(acc[u][jg * 4 + 2], 0.f),
                                           fmaxf(acc[u][jg * 4 + 3], 0.f));
                    *(float4*)(orow + e) = v;
                } else {
#pragma unroll
                    for (int m = 0; m < 4; m++)
                        if (e + m < E) orow[e + m] = fmaxf(acc[u][jg * 4 + m], 0.f);
                }
            }
        }
    }
}

// ---------------------------------------------------------------------------
// BN statistics over relu(yt), per output channel
// ---------------------------------------------------------------------------
__global__ void init_k() {
    g_sum[threadIdx.x] = 0.f;
    g_sumsq[threadIdx.x] = 0.f;
}

__global__ void stats_k(int E) {
    int c = threadIdx.x;  // 256 threads = 256 channels
    float s = 0.f, s2 = 0.f;
    int rows = B_ * E;
    for (int r = blockIdx.x; r < rows; r += gridDim.x) {
        float v = fmaxf(g_yt[(size_t)r * COUT_ + c], 0.f);
        s += v;
        s2 += v * v;
    }
    atomicAdd(&g_sum[c], s);
    atomicAdd(&g_sumsq[c], s2);
}

__global__ void scale_k(const float* __restrict__ gamma,
                        const float* __restrict__ beta, int E) {
    int c = threadIdx.x;
    float n = (float)(B_ * E);
    float mean = g_sum[c] / n;
    float var  = g_sumsq[c] / n - mean * mean;
    float a = gamma[c] * rsqrtf(var + EPSBN);
    g_a[c]   = a;
    g_bsh[c] = beta[c] - mean * a;
}

// ---------------------------------------------------------------------------
extern "C" void kernel_launch(void* const* d_in, const int* in_sizes, int n_in,
                              void* d_out, int out_size) {
    const float* x     = (const float*)d_in[0];
    const int*   gmm   = (const int*)d_in[1];
    const float* w0    = (const float*)d_in[2];
    const float* w1    = (const float*)d_in[3];
    const float* gamma = (const float*)d_in[4];
    const float* beta  = (const float*)d_in[5];
    float* out = (float*)d_out;

    int E = in_sizes[0] / (B_ * CIN_);
    if (E <= 0 || E > EMAX_) E = EMAX_;

    const int SMEM = (128 * 80 + 80 * 132) * (int)sizeof(float) + 4 * 128 * (int)sizeof(int);
    cudaFuncSetAttribute(conv_k<CIN_, false>, cudaFuncAttributeMaxDynamicSharedMemorySize, SMEM);
    cudaFuncSetAttribute(conv_k<COUT_, true>, cudaFuncAttributeMaxDynamicSharedMemorySize, SMEM);

    dim3 tgrid((E + 31) / 32, CIN_ / 32, B_);
    transpose_k<<<tgrid, dim3(32, 8)>>>(x, E);

    int etiles = (E + 127) / 128;
    conv_k<CIN_, false><<<dim3(etiles, 2, B_), 256, SMEM>>>(gmm, w0, nullptr, E);

    init_k<<<1, 256>>>();
    stats_k<<<256, 256>>>(E);
    scale_k<<<1, 256>>>(gamma, beta, E);

    conv_k<COUT_, true><<<dim3(etiles, 2, B_), 256, SMEM>>>(gmm, w1, out, E);
}

// round 2
// speedup vs baseline: 1.0313x; 1.0313x over previous
#include <cuda_runtime.h>

#define B_    4
#define CIN_  128
#define COUT_ 256
#define EMAX_ 20000
#define EPSBN 1e-5f

// Scratch (module-scope __device__ globals: no allocation at runtime)
__device__ float g_xt[(size_t)B_ * EMAX_ * CIN_];    // x transposed: [b][e][c]
__device__ float g_yt[(size_t)B_ * EMAX_ * COUT_];   // conv0 output transposed: [b][e][o]
__device__ float g_sum[COUT_];
__device__ float g_sumsq[COUT_];
__device__ float g_a[COUT_];
__device__ float g_bsh[COUT_];

// ---------------------------------------------------------------------------
// Transpose x [B][CIN][E] -> g_xt [B][E][CIN]; block (0,0,0) zeroes BN stats.
// ---------------------------------------------------------------------------
__global__ void transpose_k(const float* __restrict__ x, int E) {
    __shared__ float tile[32][33];
    if (blockIdx.x == 0 && blockIdx.y == 0 && blockIdx.z == 0) {
        int t = threadIdx.y * 32 + threadIdx.x;   // 256 threads
        g_sum[t] = 0.f;
        g_sumsq[t] = 0.f;
    }
    int b  = blockIdx.z;
    int c0 = blockIdx.y * 32;
    int e0 = blockIdx.x * 32;
    for (int r = threadIdx.y; r < 32; r += 8) {
        int c = c0 + r;
        int e = e0 + threadIdx.x;
        float v = (e < E) ? x[((size_t)b * CIN_ + c) * E + e] : 0.f;
        tile[r][threadIdx.x] = v;
    }
    __syncthreads();
    for (int r = threadIdx.y; r < 32; r += 8) {
        int e = e0 + r;
        int c = c0 + threadIdx.x;
        if (e < E) g_xt[((size_t)b * E + e) * CIN_ + c] = tile[threadIdx.x][r];
    }
}

// ---------------------------------------------------------------------------
// Fused gather + symmetric-function + GEMM, double-buffered pipeline.
//   PHASE2=false: src=g_xt, out=g_yt (transposed store) + fused BN stats
//   PHASE2=true : src=g_yt with z = a_c*relu(v)+b_c applied in the gather,
//                 out = d_out with residual (+yt) and relu.
// Block tile: 128 (out ch) x 128 (edges), K chunk = 8 ch * 5 = 40, 2 stages.
// ---------------------------------------------------------------------------
template <int CIN, bool PHASE2>
__global__ __launch_bounds__(256) void conv_k(const int* __restrict__ gmm,
                                              const float* __restrict__ w,
                                              float* __restrict__ dout, int E) {
    constexpr int KC = 8;           // channels per K chunk
    constexpr int KB = KC * 5;      // 40 K values per chunk
    constexpr int BM = 128;         // output channels per block
    constexpr int BN = 128;         // edges per block
    constexpr int GP = 132;         // padded G row (bank-conflict relief)

    extern __shared__ float smem[];
    float* Ws   = smem;                               // [2][BM][KB]
    float* Gs   = smem + 2 * BM * KB;                 // [2][KB][GP]
    int*   idxs = (int*)(smem + 2 * BM * KB + 2 * KB * GP);  // [4][BN]

    const float* src  = PHASE2 ? g_yt : g_xt;

    int tid = threadIdx.x;
    int tx = tid & 15;
    int ty = tid >> 4;
    int e0 = blockIdx.x * BN;
    int o0 = blockIdx.y * BM;
    int b  = blockIdx.z;
    const float* srcb = src + (size_t)b * E * CIN;

    // Neighbor indices for this edge tile
    for (int i = tid; i < 4 * BN; i += 256) {
        int el = i >> 2, j = i & 3;
        int eg = e0 + el;
        idxs[j * BN + el] = (eg < E) ? gmm[((size_t)b * E + eg) * 4 + j] : 0;
    }
    __syncthreads();

    // Per-thread staging coordinates
    const int ch  = tid & (KC - 1);   // 0..7
    const int elb = tid >> 3;         // 0..31

    // ---- stage chunk cc into buffer sb
    auto stage = [&](int cc, int sb) {
        int c0 = cc * KC;
        float* Wd = Ws + sb * (BM * KB);
        float* Gd = Gs + sb * (KB * GP);
        // weights: 40 contiguous floats per output channel row
#pragma unroll
        for (int q = 0; q < 5; q++) {
            int i = tid + q * 256;                 // 1280 float4 total
            int o = i / (KB / 4), kq = i % (KB / 4);
            float4 v = *(const float4*)(w + ((size_t)(o0 + o) * CIN + c0) * 5 + kq * 4);
            *(float4*)(Wd + o * KB + kq * 4) = v;
        }
        // gather + symmetric functions
        int c = c0 + ch;
        float ac = 0.f, bc = 0.f;
        if constexpr (PHASE2) { ac = g_a[c]; bc = g_bsh[c]; }
#pragma unroll
        for (int p = 0; p < BN / 32; p++) {
            int el = elb + p * 32;
            int eg = e0 + el;
            int si = (eg < E) ? eg : 0;
            int g1 = idxs[0 * BN + el];
            int g2 = idxs[1 * BN + el];
            int g3 = idxs[2 * BN + el];
            int g4 = idxs[3 * BN + el];
            float v0 = srcb[(size_t)si * CIN + c];
            float v1 = srcb[(size_t)g1 * CIN + c];
            float v2 = srcb[(size_t)g2 * CIN + c];
            float v3 = srcb[(size_t)g3 * CIN + c];
            float v4 = srcb[(size_t)g4 * CIN + c];
            if constexpr (PHASE2) {
                v0 = fmaf(ac, fmaxf(v0, 0.f), bc);
                v1 = fmaf(ac, fmaxf(v1, 0.f), bc);
                v2 = fmaf(ac, fmaxf(v2, 0.f), bc);
                v3 = fmaf(ac, fmaxf(v3, 0.f), bc);
                v4 = fmaf(ac, fmaxf(v4, 0.f), bc);
            }
            float* gp = Gd + (ch * 5) * GP + el;
            gp[0 * GP] = v0;
            gp[1 * GP] = v1 + v3;
            gp[2 * GP] = v2 + v4;
            gp[3 * GP] = fabsf(v1 - v3);
            gp[4 * GP] = fabsf(v2 - v4);
        }
    };

    float acc[8][8];
#pragma unroll
    for (int u = 0; u < 8; u++)
#pragma unroll
        for (int j = 0; j < 8; j++) acc[u][j] = 0.f;

    const int nch = CIN / KC;
    stage(0, 0);

    for (int cc = 0; cc < nch; cc++) {
        __syncthreads();
        if (cc + 1 < nch) stage(cc + 1, (cc + 1) & 1);

        const float* Wb = Ws + (cc & 1) * (BM * KB);
        const float* Gb = Gs + (cc & 1) * (KB * GP);
#pragma unroll 2
        for (int kq = 0; kq < KB / 4; kq++) {
            float br[4][8];
#pragma unroll
            for (int kk = 0; kk < 4; kk++) {
                int k = kq * 4 + kk;
                float4 t0 = *(const float4*)(Gb + k * GP + tx * 4);
                float4 t1 = *(const float4*)(Gb + k * GP + tx * 4 + 64);
                br[kk][0] = t0.x; br[kk][1] = t0.y; br[kk][2] = t0.z; br[kk][3] = t0.w;
                br[kk][4] = t1.x; br[kk][5] = t1.y; br[kk][6] = t1.z; br[kk][7] = t1.w;
            }
#pragma unroll
            for (int u = 0; u < 8; u++) {
                int ol = ty * 4 + (u & 3) + (u >> 2) * 64;
                float4 av = *(const float4*)(Wb + ol * KB + kq * 4);
                float ar[4] = {av.x, av.y, av.z, av.w};
#pragma unroll
                for (int kk = 0; kk < 4; kk++)
#pragma unroll
                    for (int j = 0; j < 8; j++)
                        acc[u][j] = fmaf(ar[kk], br[kk][j], acc[u][j]);
            }
        }
    }

    // ---- epilogue
    if constexpr (!PHASE2) {
        // store transposed: yt[b][e][o]  (pre-relu, needed as residual)
#pragma unroll
        for (int j = 0; j < 8; j++) {
            int e = e0 + tx * 4 + (j & 3) + (j >> 2) * 64;
            if (e >= E) continue;
            float* yrow = g_yt + ((size_t)b * E + e) * COUT_ + o0 + ty * 4;
            *(float4*)(yrow)      = make_float4(acc[0][j], acc[1][j], acc[2][j], acc[3][j]);
            *(float4*)(yrow + 64) = make_float4(acc[4][j], acc[5][j], acc[6][j], acc[7][j]);
        }
        // fused BN statistics over relu(y): channel o is owned by the 16
        // consecutive threads tid = ty*16 + (0..15)  -> half-warp shfl reduce
#pragma unroll
        for (int u = 0; u < 8; u++) {
            float s = 0.f, s2 = 0.f;
#pragma unroll
            for (int j = 0; j < 8; j++) {
                int e = e0 + tx * 4 + (j & 3) + (j >> 2) * 64;
                float v = (e < E) ? fmaxf(acc[u][j], 0.f) : 0.f;
                s += v;
                s2 += v * v;
            }
#pragma unroll
            for (int off = 8; off; off >>= 1) {
                s  += __shfl_down_sync(0xffffffffu, s,  off, 16);
                s2 += __shfl_down_sync(0xffffffffu, s2, off, 16);
            }
            if (tx == 0) {
                int o = o0 + ty * 4 + (u & 3) + (u >> 2) * 64;
                atomicAdd(&g_sum[o], s);
                atomicAdd(&g_sumsq[o], s2);
            }
        }
    } else {
        // residual add from yt (pre-relu conv0 output)
#pragma unroll
        for (int j = 0; j < 8; j++) {
            int e = e0 + tx * 4 + (j & 3) + (j >> 2) * 64;
            if (e >= E) continue;
            const float* yrow = g_yt + ((size_t)b * E + e) * COUT_ + o0 + ty * 4;
            float4 r0 = *(const float4*)(yrow);
            float4 r1 = *(const float4*)(yrow + 64);
            acc[0][j] += r0.x; acc[1][j] += r0.y; acc[2][j] += r0.z; acc[3][j] += r0.w;
            acc[4][j] += r1.x; acc[5][j] += r1.y; acc[6][j] += r1.z; acc[7][j] += r1.w;
        }
        // relu + store [b][o][e], coalesced float4 along e
#pragma unroll
        for (int u = 0; u < 8; u++) {
            int o = o0 + ty * 4 + (u & 3) + (u >> 2) * 64;
            float* orow = dout + ((size_t)b * COUT_ + o) * E;
#pragma unroll
            for (int jg = 0; jg < 2; jg++) {
                int e = e0 + tx * 4 + jg * 64;
                if (e + 3 < E) {
                    float4 v = make_float4(fmaxf(acc[u][jg * 4 + 0], 0.f),
                                           fmaxf(acc[u][jg * 4 + 1], 0.f),
                                           fmaxf(acc[u][jg * 4 + 2], 0.f),
                                           fmaxf(acc[u][jg * 4 + 3], 0.f));
                    *(float4*)(orow + e) = v;
                } else {
#pragma unroll
                    for (int m = 0; m < 4; m++)
                        if (e + m < E) orow[e + m] = fmaxf(acc[u][jg * 4 + m], 0.f);
                }
            }
        }
    }
}

// ---------------------------------------------------------------------------
// Turn accumulated stats into affine coefficients
// ---------------------------------------------------------------------------
__global__ void scale_k(const float* __restrict__ gamma,
                        const float* __restrict__ beta, int E) {
    int c = threadIdx.x;
    float n = (float)(B_ * E);
    float mean = g_sum[c] / n;
    float var  = g_sumsq[c] / n - mean * mean;
    float a = gamma[c] * rsqrtf(var + EPSBN);
    g_a[c]   = a;
    g_bsh[c] = beta[c] - mean * a;
}

// ---------------------------------------------------------------------------
extern "C" void kernel_launch(void* const* d_in, const int* in_sizes, int n_in,
                              void* d_out, int out_size) {
    const float* x     = (const float*)d_in[0];
    const int*   gmm   = (const int*)d_in[1];
    const float* w0    = (const float*)d_in[2];
    const float* w1    = (const float*)d_in[3];
    const float* gamma = (const float*)d_in[4];
    const float* beta  = (const float*)d_in[5];
    float* out = (float*)d_out;

    int E = in_sizes[0] / (B_ * CIN_);
    if (E <= 0 || E > EMAX_) E = EMAX_;

    const int SMEM = (2 * 128 * 40 + 2 * 40 * 132) * (int)sizeof(float)
                   + 4 * 128 * (int)sizeof(int);
    cudaFuncSetAttribute(conv_k<CIN_, false>, cudaFuncAttributeMaxDynamicSharedMemorySize, SMEM);
    cudaFuncSetAttribute(conv_k<COUT_, true>, cudaFuncAttributeMaxDynamicSharedMemorySize, SMEM);

    dim3 tgrid((E + 31) / 32, CIN_ / 32, B_);
    transpose_k<<<tgrid, dim3(32, 8)>>>(x, E);

    int etiles = (E + 127) / 128;
    conv_k<CIN_, false><<<dim3(etiles, 2, B_), 256, SMEM>>>(gmm, w0, nullptr, E);
    scale_k<<<1, 256>>>(gamma, beta, E);
    conv_k<COUT_, true><<<dim3(etiles, 2, B_), 256, SMEM>>>(gmm, w1, out, E);
}

// round 4
// speedup vs baseline: 1.2439x; 1.2062x over previous
#include <cuda_runtime.h>

#define B_    4
#define CIN_  128
#define COUT_ 256
#define EMAX_ 20000
#define EPSBN 1e-5f

// Scratch (module-scope __device__ globals: no allocation at runtime)
__device__ float g_xt[(size_t)B_ * EMAX_ * CIN_];    // x transposed: [b][e][c]
__device__ float g_yt[(size_t)B_ * EMAX_ * COUT_];   // conv0 output transposed: [b][e][o]
__device__ float g_sum[COUT_];
__device__ float g_sumsq[COUT_];
__device__ float g_a[COUT_];
__device__ float g_bsh[COUT_];

// ---------------------------------------------------------------------------
// Transpose x [B][CIN][E] -> g_xt [B][E][CIN]; block (0,0,0) zeroes BN stats.
// ---------------------------------------------------------------------------
__global__ void transpose_k(const float* __restrict__ x, int E) {
    __shared__ float tile[32][33];
    if (blockIdx.x == 0 && blockIdx.y == 0 && blockIdx.z == 0) {
        int t = threadIdx.y * 32 + threadIdx.x;   // 256 threads
        g_sum[t] = 0.f;
        g_sumsq[t] = 0.f;
    }
    int b  = blockIdx.z;
    int c0 = blockIdx.y * 32;
    int e0 = blockIdx.x * 32;
    for (int r = threadIdx.y; r < 32; r += 8) {
        int c = c0 + r;
        int e = e0 + threadIdx.x;
        float v = (e < E) ? x[((size_t)b * CIN_ + c) * E + e] : 0.f;
        tile[r][threadIdx.x] = v;
    }
    __syncthreads();
    for (int r = threadIdx.y; r < 32; r += 8) {
        int e = e0 + r;
        int c = c0 + threadIdx.x;
        if (e < E) g_xt[((size_t)b * E + e) * CIN_ + c] = tile[threadIdx.x][r];
    }
}

// ---------------------------------------------------------------------------
// Fused gather + symmetric-function + GEMM, double-buffered pipeline.
//   PHASE2=false: src=g_xt, out=g_yt (transposed store) + fused BN stats
//   PHASE2=true : src=g_yt with z = a_c*relu(v)+b_c applied in the gather,
//                 out = d_out with residual (+yt) and relu.
// Block tile: 128 (out ch) x 128 (edges), K chunk = 8 ch * 5 = 40, 2 stages.
// 2 CTAs/SM (<=128 regs), Ws padded to 44 floats/row for conflict-free LDS.
// ---------------------------------------------------------------------------
template <int CIN, bool PHASE2>
__global__ __launch_bounds__(256, 2) void conv_k(const int* __restrict__ gmm,
                                                 const float* __restrict__ w,
                                                 float* __restrict__ dout, int E) {
    constexpr int KC = 8;           // channels per K chunk
    constexpr int KB = KC * 5;      // 40 K values per chunk
    constexpr int KBP = 44;         // padded Ws row stride (bank-conflict-free)
    constexpr int BM = 128;         // output channels per block
    constexpr int BN = 128;         // edges per block
    constexpr int GP = 132;         // padded G row (bank-conflict relief)

    extern __shared__ float smem[];
    float* Ws   = smem;                               // [2][BM][KBP]
    float* Gs   = smem + 2 * BM * KBP;                // [2][KB][GP]
    int*   idxs = (int*)(smem + 2 * BM * KBP + 2 * KB * GP);  // [4][BN]

    const float* src  = PHASE2 ? g_yt : g_xt;

    int tid = threadIdx.x;
    int tx = tid & 15;
    int ty = tid >> 4;
    int e0 = blockIdx.x * BN;
    int o0 = blockIdx.y * BM;
    int b  = blockIdx.z;
    const float* srcb = src + (size_t)b * E * CIN;

    // Neighbor indices for this edge tile
    for (int i = tid; i < 4 * BN; i += 256) {
        int el = i >> 2, j = i & 3;
        int eg = e0 + el;
        idxs[j * BN + el] = (eg < E) ? gmm[((size_t)b * E + eg) * 4 + j] : 0;
    }
    __syncthreads();

    // Per-thread staging coordinates
    const int ch  = tid & (KC - 1);   // 0..7
    const int elb = tid >> 3;         // 0..31

    // ---- stage chunk cc into buffer sb
    auto stage = [&](int cc, int sb) {
        int c0 = cc * KC;
        float* Wd = Ws + sb * (BM * KBP);
        float* Gd = Gs + sb * (KB * GP);
        // weights: 40 contiguous floats per output channel row
#pragma unroll
        for (int q = 0; q < 5; q++) {
            int i = tid + q * 256;                 // 1280 float4 total
            int o = i / (KB / 4), kq = i % (KB / 4);
            float4 v = *(const float4*)(w + ((size_t)(o0 + o) * CIN + c0) * 5 + kq * 4);
            *(float4*)(Wd + o * KBP + kq * 4) = v;
        }
        // gather + symmetric functions
        int c = c0 + ch;
        float ac = 0.f, bc = 0.f;
        if constexpr (PHASE2) { ac = g_a[c]; bc = g_bsh[c]; }
#pragma unroll
        for (int p = 0; p < BN / 32; p++) {
            int el = elb + p * 32;
            int eg = e0 + el;
            int si = (eg < E) ? eg : 0;
            int g1 = idxs[0 * BN + el];
            int g2 = idxs[1 * BN + el];
            int g3 = idxs[2 * BN + el];
            int g4 = idxs[3 * BN + el];
            float v0 = srcb[(size_t)si * CIN + c];
            float v1 = srcb[(size_t)g1 * CIN + c];
            float v2 = srcb[(size_t)g2 * CIN + c];
            float v3 = srcb[(size_t)g3 * CIN + c];
            float v4 = srcb[(size_t)g4 * CIN + c];
            if constexpr (PHASE2) {
                v0 = fmaf(ac, fmaxf(v0, 0.f), bc);
                v1 = fmaf(ac, fmaxf(v1, 0.f), bc);
                v2 = fmaf(ac, fmaxf(v2, 0.f), bc);
                v3 = fmaf(ac, fmaxf(v3, 0.f), bc);
                v4 = fmaf(ac, fmaxf(v4, 0.f), bc);
            }
            float* gp = Gd + (ch * 5) * GP + el;
            gp[0 * GP] = v0;
            gp[1 * GP] = v1 + v3;
            gp[2 * GP] = v2 + v4;
            gp[3 * GP] = fabsf(v1 - v3);
            gp[4 * GP] = fabsf(v2 - v4);
        }
    };

    float acc[8][8];
#pragma unroll
    for (int u = 0; u < 8; u++)
#pragma unroll
        for (int j = 0; j < 8; j++) acc[u][j] = 0.f;

    const int nch = CIN / KC;
    stage(0, 0);

    for (int cc = 0; cc < nch; cc++) {
        __syncthreads();
        if (cc + 1 < nch) stage(cc + 1, (cc + 1) & 1);

        const float* Wb = Ws + (cc & 1) * (BM * KBP);
        const float* Gb = Gs + (cc & 1) * (KB * GP);
#pragma unroll 2
        for (int kq = 0; kq < KB / 4; kq++) {
            float br[4][8];
#pragma unroll
            for (int kk = 0; kk < 4; kk++) {
                int k = kq * 4 + kk;
                float4 t0 = *(const float4*)(Gb + k * GP + tx * 4);
                float4 t1 = *(const float4*)(Gb + k * GP + tx * 4 + 64);
                br[kk][0] = t0.x; br[kk][1] = t0.y; br[kk][2] = t0.z; br[kk][3] = t0.w;
                br[kk][4] = t1.x; br[kk][5] = t1.y; br[kk][6] = t1.z; br[kk][7] = t1.w;
            }
#pragma unroll
            for (int u = 0; u < 8; u++) {
                int ol = ty * 4 + (u & 3) + (u >> 2) * 64;
                float4 av = *(const float4*)(Wb + ol * KBP + kq * 4);
                float ar[4] = {av.x, av.y, av.z, av.w};
#pragma unroll
                for (int kk = 0; kk < 4; kk++)
#pragma unroll
                    for (int j = 0; j < 8; j++)
                        acc[u][j] = fmaf(ar[kk], br[kk][j], acc[u][j]);
            }
        }
    }

    // ---- epilogue
    if constexpr (!PHASE2) {
        // store transposed: yt[b][e][o]  (pre-relu, needed as residual)
#pragma unroll
        for (int j = 0; j < 8; j++) {
            int e = e0 + tx * 4 + (j & 3) + (j >> 2) * 64;
            if (e >= E) continue;
            float* yrow = g_yt + ((size_t)b * E + e) * COUT_ + o0 + ty * 4;
            *(float4*)(yrow)      = make_float4(acc[0][j], acc[1][j], acc[2][j], acc[3][j]);
            *(float4*)(yrow + 64) = make_float4(acc[4][j], acc[5][j], acc[6][j], acc[7][j]);
        }
        // fused BN statistics over relu(y): channel o is owned by the 16
        // consecutive threads tid = ty*16 + (0..15)  -> half-warp shfl reduce
#pragma unroll
        for (int u = 0; u < 8; u++) {
            float s = 0.f, s2 = 0.f;
#pragma unroll
            for (int j = 0; j < 8; j++) {
                int e = e0 + tx * 4 + (j & 3) + (j >> 2) * 64;
                float v = (e < E) ? fmaxf(acc[u][j], 0.f) : 0.f;
                s += v;
                s2 += v * v;
            }
#pragma unroll
            for (int off = 8; off; off >>= 1) {
                s  += __shfl_down_sync(0xffffffffu, s,  off, 16);
                s2 += __shfl_down_sync(0xffffffffu, s2, off, 16);
            }
            if (tx == 0) {
                int o = o0 + ty * 4 + (u & 3) + (u >> 2) * 64;
                atomicAdd(&g_sum[o], s);
                atomicAdd(&g_sumsq[o], s2);
            }
        }
    } else {
        // residual add from yt (pre-relu conv0 output)
#pragma unroll
        for (int j = 0; j < 8; j++) {
            int e = e0 + tx * 4 + (j & 3) + (j >> 2) * 64;
            if (e >= E) continue;
            const float* yrow = g_yt + ((size_t)b * E + e) * COUT_ + o0 + ty * 4;
            float4 r0 = *(const float4*)(yrow);
            float4 r1 = *(const float4*)(yrow + 64);
            acc[0][j] += r0.x; acc[1][j] += r0.y; acc[2][j] += r0.z; acc[3][j] += r0.w;
            acc[4][j] += r1.x; acc[5][j] += r1.y; acc[6][j] += r1.z; acc[7][j] += r1.w;
        }
        // relu + store [b][o][e], coalesced float4 along e
#pragma unroll
        for (int u = 0; u < 8; u++) {
            int o = o0 + ty * 4 + (u & 3) + (u >> 2) * 64;
            float* orow = dout + ((size_t)b * COUT_ + o) * E;
#pragma unroll
            for (int jg = 0; jg < 2; jg++) {
                int e = e0 + tx * 4 + jg * 64;
                if (e + 3 < E) {
                    float4 v = make_float4(fmaxf(acc[u][jg * 4 + 0], 0.f),
                                           fmaxf(acc[u][jg * 4 + 1], 0.f),
                                           fmaxf(acc[u][jg * 4 + 2], 0.f),
                                           fmaxf(acc[u][jg * 4 + 3], 0.f));
                    *(float4*)(orow + e) = v;
                } else {
#pragma unroll
                    for (int m = 0; m < 4; m++)
                        if (e + m < E) orow[e + m] = fmaxf(acc[u][jg * 4 + m], 0.f);
                }
            }
        }
    }
}

// ---------------------------------------------------------------------------
// Turn accumulated stats into affine coefficients
// ---------------------------------------------------------------------------
__global__ void scale_k(const float* __restrict__ gamma,
                        const float* __restrict__ beta, int E) {
    int c = threadIdx.x;
    float n = (float)(B_ * E);
    float mean = g_sum[c] / n;
    float var  = g_sumsq[c] / n - mean * mean;
    float a = gamma[c] * rsqrtf(var + EPSBN);
    g_a[c]   = a;
    g_bsh[c] = beta[c] - mean * a;
}

// ---------------------------------------------------------------------------
extern "C" void kernel_launch(void* const* d_in, const int* in_sizes, int n_in,
                              void* d_out, int out_size) {
    const float* x     = (const float*)d_in[0];
    const int*   gmm   = (const int*)d_in[1];
    const float* w0    = (const float*)d_in[2];
    const float* w1    = (const float*)d_in[3];
    const float* gamma = (const float*)d_in[4];
    const float* beta  = (const float*)d_in[5];
    float* out = (float*)d_out;

    int E = in_sizes[0] / (B_ * CIN_);
    if (E <= 0 || E > EMAX_) E = EMAX_;

    const int SMEM = (2 * 128 * 44 + 2 * 40 * 132) * (int)sizeof(float)
                   + 4 * 128 * (int)sizeof(int);
    cudaFuncSetAttribute(conv_k<CIN_, false>, cudaFuncAttributeMaxDynamicSharedMemorySize, SMEM);
    cudaFuncSetAttribute(conv_k<COUT_, true>, cudaFuncAttributeMaxDynamicSharedMemorySize, SMEM);

    dim3 tgrid((E + 31) / 32, CIN_ / 32, B_);
    transpose_k<<<tgrid, dim3(32, 8)>>>(x, E);

    int etiles = (E + 127) / 128;
    conv_k<CIN_, false><<<dim3(etiles, 2, B_), 256, SMEM>>>(gmm, w0, nullptr, E);
    scale_k<<<1, 256>>>(gamma, beta, E);
    conv_k<COUT_, true><<<dim3(etiles, 2, B_), 256, SMEM>>>(gmm, w1, out, E);
}

// round 6
// speedup vs baseline: 1.2836x; 1.0319x over previous
#include <cuda_runtime.h>

#define B_    4
#define CIN_  128
#define COUT_ 256
#define EMAX_ 20000
#define EPSBN 1e-5f

typedef unsigned long long u64;

// Packed fp32x2 helpers (Blackwell FFMA2 — PTX-only, ptxas won't auto-fuse)
__device__ __forceinline__ u64 pack2(float lo, float hi) {
    u64 r; asm("mov.b64 %0, {%1, %2};" : "=l"(r) : "f"(lo), "f"(hi)); return r;
}
__device__ __forceinline__ void unpack2(float& lo, float& hi, u64 v) {
    asm("mov.b64 {%0, %1}, %2;" : "=f"(lo), "=f"(hi) : "l"(v));
}
__device__ __forceinline__ void ffma2(u64& d, u64 a, u64 b) {
    asm("fma.rn.f32x2 %0, %1, %2, %0;" : "+l"(d) : "l"(a), "l"(b));
}

// Scratch (module-scope __device__ globals: no allocation at runtime)
__device__ float g_xt[(size_t)B_ * EMAX_ * CIN_];    // x transposed: [b][e][c]
__device__ float g_yt[(size_t)B_ * EMAX_ * COUT_];   // conv0 output transposed: [b][e][o]
__device__ float g_sum[COUT_];
__device__ float g_sumsq[COUT_];
__device__ float g_a[COUT_];
__device__ float g_bsh[COUT_];

// ---------------------------------------------------------------------------
// Transpose x [B][CIN][E] -> g_xt [B][E][CIN]; block (0,0,0) zeroes BN stats.
// ---------------------------------------------------------------------------
__global__ void transpose_k(const float* __restrict__ x, int E) {
    __shared__ float tile[32][33];
    if (blockIdx.x == 0 && blockIdx.y == 0 && blockIdx.z == 0) {
        int t = threadIdx.y * 32 + threadIdx.x;   // 256 threads
        g_sum[t] = 0.f;
        g_sumsq[t] = 0.f;
    }
    int b  = blockIdx.z;
    int c0 = blockIdx.y * 32;
    int e0 = blockIdx.x * 32;
    for (int r = threadIdx.y; r < 32; r += 8) {
        int c = c0 + r;
        int e = e0 + threadIdx.x;
        float v = (e < E) ? x[((size_t)b * CIN_ + c) * E + e] : 0.f;
        tile[r][threadIdx.x] = v;
    }
    __syncthreads();
    for (int r = threadIdx.y; r < 32; r += 8) {
        int e = e0 + r;
        int c = c0 + threadIdx.x;
        if (e < E) g_xt[((size_t)b * E + e) * CIN_ + c] = tile[threadIdx.x][r];
    }
}

// ---------------------------------------------------------------------------
// Fused gather + symmetric-function + GEMM, double-buffered, FFMA2 mainloop.
//   PHASE2=false: src=g_xt, out=g_yt (transposed store) + fused BN stats
//   PHASE2=true : src=g_yt with z = a_c*relu(v)+b_c applied in the gather,
//                 out = d_out with residual (+yt) and relu.
// ---------------------------------------------------------------------------
template <int CIN, bool PHASE2>
__global__ __launch_bounds__(256, 2) void conv_k(const int* __restrict__ gmm,
                                                 const float* __restrict__ w,
                                                 float* __restrict__ dout, int E) {
    constexpr int KC = 8;           // channels per K chunk
    constexpr int KB = KC * 5;      // 40 K values per chunk
    constexpr int KBP = 44;         // padded Ws row stride (bank-conflict-free)
    constexpr int BM = 128;         // output channels per block
    constexpr int BN = 128;         // edges per block
    constexpr int GP = 132;         // padded G row (bank-conflict relief)

    extern __shared__ float smem[];
    float* Ws   = smem;                               // [2][BM][KBP]
    float* Gs   = smem + 2 * BM * KBP;                // [2][KB][GP]
    int*   idxs = (int*)(smem + 2 * BM * KBP + 2 * KB * GP);  // [4][BN]

    const float* src  = PHASE2 ? g_yt : g_xt;

    int tid = threadIdx.x;
    int tx = tid & 15;
    int ty = tid >> 4;
    int e0 = blockIdx.x * BN;
    int o0 = blockIdx.y * BM;
    int b  = blockIdx.z;
    const float* srcb = src + (size_t)b * E * CIN;

    // Neighbor indices for this edge tile
    for (int i = tid; i < 4 * BN; i += 256) {
        int el = i >> 2, j = i & 3;
        int eg = e0 + el;
        idxs[j * BN + el] = (eg < E) ? gmm[((size_t)b * E + eg) * 4 + j] : 0;
    }
    __syncthreads();

    // Per-thread staging coordinates
    const int ch  = tid & (KC - 1);   // 0..7
    const int elb = tid >> 3;         // 0..31

    // ---- stage chunk cc into buffer sb
    auto stage = [&](int cc, int sb) {
        int c0 = cc * KC;
        float* Wd = Ws + sb * (BM * KBP);
        float* Gd = Gs + sb * (KB * GP);
        // weights: 40 contiguous floats per output channel row
#pragma unroll
        for (int q = 0; q < 5; q++) {
            int i = tid + q * 256;                 // 1280 float4 total
            int o = i / (KB / 4), kq = i % (KB / 4);
            float4 v = *(const float4*)(w + ((size_t)(o0 + o) * CIN + c0) * 5 + kq * 4);
            *(float4*)(Wd + o * KBP + kq * 4) = v;
        }
        // gather + symmetric functions
        int c = c0 + ch;
        float ac = 0.f, bc = 0.f;
        if constexpr (PHASE2) { ac = g_a[c]; bc = g_bsh[c]; }
#pragma unroll
        for (int p = 0; p < BN / 32; p++) {
            int el = elb + p * 32;
            int eg = e0 + el;
            int si = (eg < E) ? eg : 0;
            int g1 = idxs[0 * BN + el];
            int g2 = idxs[1 * BN + el];
            int g3 = idxs[2 * BN + el];
            int g4 = idxs[3 * BN + el];
            float v0 = srcb[(size_t)si * CIN + c];
            float v1 = srcb[(size_t)g1 * CIN + c];
            float v2 = srcb[(size_t)g2 * CIN + c];
            float v3 = srcb[(size_t)g3 * CIN + c];
            float v4 = srcb[(size_t)g4 * CIN + c];
            if constexpr (PHASE2) {
                v0 = fmaf(ac, fmaxf(v0, 0.f), bc);
                v1 = fmaf(ac, fmaxf(v1, 0.f), bc);
                v2 = fmaf(ac, fmaxf(v2, 0.f), bc);
                v3 = fmaf(ac, fmaxf(v3, 0.f), bc);
                v4 = fmaf(ac, fmaxf(v4, 0.f), bc);
            }
            float* gp = Gd + (ch * 5) * GP + el;
            gp[0 * GP] = v0;
            gp[1 * GP] = v1 + v3;
            gp[2 * GP] = v2 + v4;
            gp[3 * GP] = fabsf(v1 - v3);
            gp[4 * GP] = fabsf(v2 - v4);
        }
    };

    // Packed accumulators: acc2[u][jp] holds edges (2*jp, 2*jp+1) of row u
    u64 acc2[8][4];
#pragma unroll
    for (int u = 0; u < 8; u++)
#pragma unroll
        for (int jp = 0; jp < 4; jp++) acc2[u][jp] = 0ull;

    const int nch = CIN / KC;
    stage(0, 0);

    for (int cc = 0; cc < nch; cc++) {
        __syncthreads();
        if (cc + 1 < nch) stage(cc + 1, (cc + 1) & 1);

        const float* Wb = Ws + (cc & 1) * (BM * KBP);
        const float* Gb = Gs + (cc & 1) * (KB * GP);
#pragma unroll 2
        for (int kq = 0; kq < KB / 4; kq++) {
            u64 brp[4][4];
#pragma unroll
            for (int kk = 0; kk < 4; kk++) {
                int k = kq * 4 + kk;
                float4 t0 = *(const float4*)(Gb + k * GP + tx * 4);
                float4 t1 = *(const float4*)(Gb + k * GP + tx * 4 + 64);
                brp[kk][0] = pack2(t0.x, t0.y);
                brp[kk][1] = pack2(t0.z, t0.w);
                brp[kk][2] = pack2(t1.x, t1.y);
                brp[kk][3] = pack2(t1.z, t1.w);
            }
#pragma unroll
            for (int u = 0; u < 8; u++) {
                int ol = ty * 4 + (u & 3) + (u >> 2) * 64;
                float4 av = *(const float4*)(Wb + ol * KBP + kq * 4);
                u64 a0 = pack2(av.x, av.x);
                u64 a1 = pack2(av.y, av.y);
                u64 a2 = pack2(av.z, av.z);
                u64 a3 = pack2(av.w, av.w);
#pragma unroll
                for (int jp = 0; jp < 4; jp++) ffma2(acc2[u][jp], a0, brp[0][jp]);
#pragma unroll
                for (int jp = 0; jp < 4; jp++) ffma2(acc2[u][jp], a1, brp[1][jp]);
#pragma unroll
                for (int jp = 0; jp < 4; jp++) ffma2(acc2[u][jp], a2, brp[2][jp]);
#pragma unroll
                for (int jp = 0; jp < 4; jp++) ffma2(acc2[u][jp], a3, brp[3][jp]);
            }
        }
    }

    // Unpack accumulators
    float acc[8][8];
#pragma unroll
    for (int u = 0; u < 8; u++)
#pragma unroll
        for (int jp = 0; jp < 4; jp++)
            unpack2(acc[u][2 * jp], acc[u][2 * jp + 1], acc2[u][jp]);

    // ---- epilogue
    if constexpr (!PHASE2) {
        // store transposed: yt[b][e][o]  (pre-relu, needed as residual)
#pragma unroll
        for (int j = 0; j < 8; j++) {
            int e = e0 + tx * 4 + (j & 3) + (j >> 2) * 64;
            if (e >= E) continue;
            float* yrow = g_yt + ((size_t)b * E + e) * COUT_ + o0 + ty * 4;
            *(float4*)(yrow)      = make_float4(acc[0][j], acc[1][j], acc[2][j], acc[3][j]);
            *(float4*)(yrow + 64) = make_float4(acc[4][j], acc[5][j], acc[6][j], acc[7][j]);
        }
        // fused BN statistics over relu(y): half-warp shfl reduce per channel
#pragma unroll
        for (int u = 0; u < 8; u++) {
            float s = 0.f, s2 = 0.f;
#pragma unroll
            for (int j = 0; j < 8; j++) {
                int e = e0 + tx * 4 + (j & 3) + (j >> 2) * 64;
                float v = (e < E) ? fmaxf(acc[u][j], 0.f) : 0.f;
                s += v;
                s2 += v * v;
            }
#pragma unroll
            for (int off = 8; off; off >>= 1) {
                s  += __shfl_down_sync(0xffffffffu, s,  off, 16);
                s2 += __shfl_down_sync(0xffffffffu, s2, off, 16);
            }
            if (tx == 0) {
                int o = o0 + ty * 4 + (u & 3) + (u >> 2) * 64;
                atomicAdd(&g_sum[o], s);
                atomicAdd(&g_sumsq[o], s2);
            }
        }
    } else {
        // residual add from yt (pre-relu conv0 output)
#pragma unroll
        for (int j = 0; j < 8; j++) {
            int e = e0 + tx * 4 + (j & 3) + (j >> 2) * 64;
            if (e >= E) continue;
            const float* yrow = g_yt + ((size_t)b * E + e) * COUT_ + o0 + ty * 4;
            float4 r0 = *(const float4*)(yrow);
            float4 r1 = *(const float4*)(yrow + 64);
            acc[0][j] += r0.x; acc[1][j] += r0.y; acc[2][j] += r0.z; acc[3][j] += r0.w;
            acc[4][j] += r1.x; acc[5][j] += r1.y; acc[6][j] += r1.z; acc[7][j] += r1.w;
        }
        // relu + store [b][o][e], coalesced float4 along e
#pragma unroll
        for (int u = 0; u < 8; u++) {
            int o = o0 + ty * 4 + (u & 3) + (u >> 2) * 64;
            float* orow = dout + ((size_t)b * COUT_ + o) * E;
#pragma unroll
            for (int jg = 0; jg < 2; jg++) {
                int e = e0 + tx * 4 + jg * 64;
                if (e + 3 < E) {
                    float4 v = make_float4(fmaxf(acc[u][jg * 4 + 0], 0.f),
                                           fmaxf(acc[u][jg * 4 + 1], 0.f),
                                           fmaxf(acc[u][jg * 4 + 2], 0.f),
                                           fmaxf(acc[u][jg * 4 + 3], 0.f));
                    *(float4*)(orow + e) = v;
                } else {
#pragma unroll
                    for (int m = 0; m < 4; m++)
                        if (e + m < E) orow[e + m] = fmaxf(acc[u][jg * 4 + m], 0.f);
                }
            }
        }
    }
}

// ---------------------------------------------------------------------------
// Turn accumulated stats into affine coefficients
// ---------------------------------------------------------------------------
__global__ void scale_k(const float* __restrict__ gamma,
                        const float* __restrict__ beta, int E) {
    int c = threadIdx.x;
    float n = (float)(B_ * E);
    float mean = g_sum[c] / n;
    float var  = g_sumsq[c] / n - mean * mean;
    float a = gamma[c] * rsqrtf(var + EPSBN);
    g_a[c]   = a;
    g_bsh[c] = beta[c] - mean * a;
}

// ---------------------------------------------------------------------------
extern "C" void kernel_launch(void* const* d_in, const int* in_sizes, int n_in,
                              void* d_out, int out_size) {
    const float* x     = (const float*)d_in[0];
    const int*   gmm   = (const int*)d_in[1];
    const float* w0    = (const float*)d_in[2];
    const float* w1    = (const float*)d_in[3];
    const float* gamma = (const float*)d_in[4];
    const float* beta  = (const float*)d_in[5];
    float* out = (float*)d_out;

    int E = in_sizes[0] / (B_ * CIN_);
    if (E <= 0 || E > EMAX_) E = EMAX_;

    const int SMEM = (2 * 128 * 44 + 2 * 40 * 132) * (int)sizeof(float)
                   + 4 * 128 * (int)sizeof(int);
    cudaFuncSetAttribute(conv_k<CIN_, false>, cudaFuncAttributeMaxDynamicSharedMemorySize, SMEM);
    cudaFuncSetAttribute(conv_k<COUT_, true>, cudaFuncAttributeMaxDynamicSharedMemorySize, SMEM);

    dim3 tgrid((E + 31) / 32, CIN_ / 32, B_);
    transpose_k<<<tgrid, dim3(32, 8)>>>(x, E);

    int etiles = (E + 127) / 128;
    conv_k<CIN_, false><<<dim3(etiles, 2, B_), 256, SMEM>>>(gmm, w0, nullptr, E);
    scale_k<<<1, 256>>>(gamma, beta, E);
    conv_k<COUT_, true><<<dim3(etiles, 2, B_), 256, SMEM>>>(gmm, w1, out, E);
}

// round 9
// speedup vs baseline: 1.6950x; 1.3206x over previous
#include <cuda_runtime.h>
#include <cuda_bf16.h>
#include <cstdint>

typedef uint32_t u32;

#define B_    4
#define CIN_  128
#define COUT_ 256
#define EMAX_ 20000
#define EPSBN 1e-5f

// ---------------- device scratch (no runtime allocation) ----------------
__device__ float g_xt[(size_t)B_ * EMAX_ * CIN_];    // x transposed [b][e][c]
__device__ float g_yt[(size_t)B_ * EMAX_ * COUT_];   // conv0 out [b][e][o]
__device__ float g_sum[COUT_];
__device__ float g_sumsq[COUT_];
__device__ float g_a[COUT_];
__device__ float g_bsh[COUT_];

__device__ __forceinline__ u32 pkbf(__nv_bfloat16 a, __nv_bfloat16 b) {
    __nv_bfloat162 t;
    t.x = a; t.y = b;
    return *reinterpret_cast<u32*>(&t);
}

#define MMA_BF16(d, a0, a1, b0) \
    asm volatile("mma.sync.aligned.m16n8k8.row.col.f32.bf16.bf16.f32 " \
                 "{%0,%1,%2,%3}, {%4,%5}, {%6}, {%0,%1,%2,%3};" \
                 : "+f"((d)[0]), "+f"((d)[1]), "+f"((d)[2]), "+f"((d)[3]) \
                 : "r"(a0), "r"(a1), "r"(b0))

// ---------------------------------------------------------------------------
// Transpose x [B][CIN][E] -> g_xt [B][E][CIN]; block (0,0,0) zeroes BN stats.
// ---------------------------------------------------------------------------
__global__ void transpose_k(const float* __restrict__ x, int E) {
    __shared__ float tile[32][33];
    if (blockIdx.x == 0 && blockIdx.y == 0 && blockIdx.z == 0) {
        int t = threadIdx.y * 32 + threadIdx.x;
        g_sum[t] = 0.f;
        g_sumsq[t] = 0.f;
    }
    int b  = blockIdx.z;
    int c0 = blockIdx.y * 32;
    int e0 = blockIdx.x * 32;
    for (int r = threadIdx.y; r < 32; r += 8) {
        int c = c0 + r, e = e0 + threadIdx.x;
        tile[r][threadIdx.x] = (e < E) ? x[((size_t)b * CIN_ + c) * E + e] : 0.f;
    }
    __syncthreads();
    for (int r = threadIdx.y; r < 32; r += 8) {
        int e = e0 + r, c = c0 + threadIdx.x;
        if (e < E) g_xt[((size_t)b * E + e) * CIN_ + c] = tile[threadIdx.x][r];
    }
}

// ---------------------------------------------------------------------------
// Fused gather + symmetric funcs + bf16-split tensor-core GEMM (mma.sync).
// Tile: M=128 (out ch) x N=128 (edges); K chunk = 8 ch * 5 = 40 bf16 values.
// D = Whi*Ghi + Whi*Glo + Wlo*Ghi  (fp32 accum; lo*lo term ~2^-18, dropped)
// W staged [o][k] bf16, G staged [e][k] bf16 (row.col mma operands).
// Double-buffered, 2 CTAs/SM.
// ---------------------------------------------------------------------------
template <int CIN, bool PHASE2>
__global__ __launch_bounds__(256, 2) void conv_m(const int* __restrict__ gmm,
                                                 const float* __restrict__ w,
                                                 float* __restrict__ dout, int E) {
    constexpr int KC = 8;
    constexpr int KB = KC * 5;          // 40 k values per chunk
    constexpr int RW = KB / 2;          // 20 u32 words per bf16 row
    constexpr int TILE = 128 * RW;      // words per operand tile (10240 B)
    constexpr int TDS = 132;            // Td row stride (floats)

    extern __shared__ u32 sm32[];
    int* idxs  = (int*)sm32;            // [4][128]  (2048 B)
    u32* tiles = sm32 + 1024;           // buffers at byte 4096
    float* Td  = (float*)(sm32 + 1024); // epilogue overlay [128][TDS]

    const int tid = threadIdx.x;
    const int wid = tid >> 5;
    const int lane = tid & 31;
    const int gid = lane >> 2;
    const int t4  = lane & 3;
    const int e0 = blockIdx.x * 128;
    const int o0 = blockIdx.y * 128;
    const int b  = blockIdx.z;
    const float* srcb = (PHASE2 ? g_yt : g_xt) + (size_t)b * E * CIN;

    // warp tile: 32 (M) x 64 (N)
    const int m0 = (wid & 3) * 32;
    const int n0 = (wid >> 2) * 64;

    for (int i = tid; i < 512; i += 256) {
        int el = i >> 2, j = i & 3;
        int eg = e0 + el;
        idxs[j * 128 + el] = (eg < E) ? gmm[((size_t)b * E + eg) * 4 + j] : 0;
    }
    __syncthreads();

    const int ch  = tid & (KC - 1);
    const int elb = tid >> 3;

    auto stage = [&](int cc, int sb) {
        u32* Wh = tiles + sb * 4 * TILE;
        u32* Wl = Wh + TILE;
        u32* Gh = Wh + 2 * TILE;
        u32* Gl = Wh + 3 * TILE;
        // ---- weights: 40 contiguous floats per o row (k = (c-c0)*5+s)
#pragma unroll
        for (int q = 0; q < 5; q++) {
            int i = tid + q * 256;
            int o = i / 10, kq = i % 10;
            float4 v = *(const float4*)(w + ((size_t)(o0 + o) * CIN + cc * KC) * 5 + kq * 4);
            __nv_bfloat16 hx = __float2bfloat16_rn(v.x);
            __nv_bfloat16 hy = __float2bfloat16_rn(v.y);
            __nv_bfloat16 hz = __float2bfloat16_rn(v.z);
            __nv_bfloat16 hw = __float2bfloat16_rn(v.w);
            __nv_bfloat16 lx = __float2bfloat16_rn(v.x - __bfloat162float(hx));
            __nv_bfloat16 ly = __float2bfloat16_rn(v.y - __bfloat162float(hy));
            __nv_bfloat16 lz = __float2bfloat16_rn(v.z - __bfloat162float(hz));
            __nv_bfloat16 lw = __float2bfloat16_rn(v.w - __bfloat162float(hw));
            int widx = o * RW + kq * 2;
            *(uint2*)(Wh + widx) = make_uint2(pkbf(hx, hy), pkbf(hz, hw));
            *(uint2*)(Wl + widx) = make_uint2(pkbf(lx, ly), pkbf(lz, lw));
        }
        // ---- gather + symmetric functions -> G[e][k] bf16 hi/lo
        int c = cc * KC + ch;
        float ac = 0.f, bc = 0.f;
        if constexpr (PHASE2) { ac = g_a[c]; bc = g_bsh[c]; }
#pragma unroll
        for (int p = 0; p < 4; p++) {
            int el = elb + p * 32;
            int eg = e0 + el;
            int si = (eg < E) ? eg : 0;
            int g1 = idxs[0 * 128 + el];
            int g2 = idxs[1 * 128 + el];
            int g3 = idxs[2 * 128 + el];
            int g4 = idxs[3 * 128 + el];
            float v0 = srcb[(size_t)si * CIN + c];
            float v1 = srcb[(size_t)g1 * CIN + c];
            float v2 = srcb[(size_t)g2 * CIN + c];
            float v3 = srcb[(size_t)g3 * CIN + c];
            float v4 = srcb[(size_t)g4 * CIN + c];
            if constexpr (PHASE2) {
                v0 = fmaf(ac, fmaxf(v0, 0.f), bc);
                v1 = fmaf(ac, fmaxf(v1, 0.f), bc);
                v2 = fmaf(ac, fmaxf(v2, 0.f), bc);
                v3 = fmaf(ac, fmaxf(v3, 0.f), bc);
                v4 = fmaf(ac, fmaxf(v4, 0.f), bc);
            }
            float f[5];
            f[0] = v0;
            f[1] = v1 + v3;
            f[2] = v2 + v4;
            f[3] = fabsf(v1 - v3);
            f[4] = fabsf(v2 - v4);
            __nv_bfloat16* gh = (__nv_bfloat16*)Gh + el * KB + ch * 5;
            __nv_bfloat16* gl = (__nv_bfloat16*)Gl + el * KB + ch * 5;
#pragma unroll
            for (int s = 0; s < 5; s++) {
                __nv_bfloat16 h = __float2bfloat16_rn(f[s]);
                gh[s] = h;
                gl[s] = __float2bfloat16_rn(f[s] - __bfloat162float(h));
            }
        }
    };

    float acc[2][8][4];
#pragma unroll
    for (int mt = 0; mt < 2; mt++)
#pragma unroll
        for (int nt = 0; nt < 8; nt++)
#pragma unroll
            for (int cq = 0; cq < 4; cq++) acc[mt][nt][cq] = 0.f;

    const int nch = CIN / KC;
    stage(0, 0);

    for (int cc = 0; cc < nch; cc++) {
        __syncthreads();
        if (cc + 1 < nch) stage(cc + 1, (cc + 1) & 1);

        const u32* Wh = tiles + (cc & 1) * 4 * TILE;
        const u32* Wl = Wh + TILE;
        const u32* Gh = Wh + 2 * TILE;
        const u32* Gl = Wh + 3 * TILE;
#pragma unroll
        for (int ks = 0; ks < 5; ks++) {
            int kwd = ks * 4 + t4;
            u32 ah[2][2], al[2][2];
#pragma unroll
            for (int mt = 0; mt < 2; mt++) {
                int base = (m0 + mt * 16 + gid) * RW + kwd;
                ah[mt][0] = Wh[base];
                ah[mt][1] = Wh[base + 8 * RW];
                al[mt][0] = Wl[base];
                al[mt][1] = Wl[base + 8 * RW];
            }
#pragma unroll
            for (int nt = 0; nt < 8; nt++) {
                int bb = (n0 + nt * 8 + gid) * RW + kwd;
                u32 bh = Gh[bb];
                u32 bl = Gl[bb];
#pragma unroll
                for (int mt = 0; mt < 2; mt++) {
                    MMA_BF16(acc[mt][nt], ah[mt][0], ah[mt][1], bh);
                    MMA_BF16(acc[mt][nt], ah[mt][0], ah[mt][1], bl);
                    MMA_BF16(acc[mt][nt], al[mt][0], al[mt][1], bh);
                }
            }
        }
    }

    // ---- epilogue: dump accumulators to Td[e][o] (overlays ring buffers)
    __syncthreads();
#pragma unroll
    for (int mt = 0; mt < 2; mt++)
#pragma unroll
        for (int nt = 0; nt < 8; nt++)
#pragma unroll
            for (int cq = 0; cq < 4; cq++) {
                int ol = m0 + mt * 16 + gid + (cq >> 1) * 8;
                int el = n0 + nt * 8 + t4 * 2 + (cq & 1);
                Td[el * TDS + ol] = acc[mt][nt][cq];
            }
    __syncthreads();

    if constexpr (!PHASE2) {
        // BN stats: thread owns channel o = tid&127 over half the e rows
        {
            int ol = tid & 127, h = tid >> 7;
            float s = 0.f, s2 = 0.f;
            for (int r = 0; r < 64; r++) {
                int el = h * 64 + r;
                if (e0 + el < E) {
                    float v = fmaxf(Td[el * TDS + ol], 0.f);
                    s += v;
                    s2 += v * v;
                }
            }
            atomicAdd(&g_sum[o0 + ol], s);
            atomicAdd(&g_sumsq[o0 + ol], s2);
        }
        // coalesced yt store (pre-relu)
        for (int i = tid; i < 128 * 32; i += 256) {
            int el = i >> 5, q = i & 31;
            int e = e0 + el;
            if (e < E)
                *(float4*)&g_yt[((size_t)b * E + e) * COUT_ + o0 + q * 4] =
                    *(float4*)&Td[el * TDS + q * 4];
        }
    } else {
        // residual + relu in Td (coalesced yt rows)
        for (int i = tid; i < 128 * 32; i += 256) {
            int el = i >> 5, q = i & 31;
            int e = e0 + el;
            if (e < E) {
                float4 r = *(const float4*)&g_yt[((size_t)b * E + e) * COUT_ + o0 + q * 4];
                float4 t = *(float4*)&Td[el * TDS + q * 4];
                t.x = fmaxf(t.x + r.x, 0.f);
                t.y = fmaxf(t.y + r.y, 0.f);
                t.z = fmaxf(t.z + r.z, 0.f);
                t.w = fmaxf(t.w + r.w, 0.f);
                *(float4*)&Td[el * TDS + q * 4] = t;
            }
        }
        __syncthreads();
        // transposed store out[b][o][e] (scalar, coalesced along e)
        for (int i = tid; i < 128 * 128; i += 256) {
            int el = i & 127, ol = i >> 7;
            int e = e0 + el;
            if (e < E)
                dout[((size_t)b * COUT_ + o0 + ol) * E + e] = Td[el * TDS + ol];
        }
    }
}

// ---------------------------------------------------------------------------
__global__ void scale_k(const float* __restrict__ gamma,
                        const float* __restrict__ beta, int E) {
    int c = threadIdx.x;
    float n = (float)(B_ * E);
    float mean = g_sum[c] / n;
    float var  = g_sumsq[c] / n - mean * mean;
    float a = gamma[c] * rsqrtf(var + EPSBN);
    g_a[c]   = a;
    g_bsh[c] = beta[c] - mean * a;
}

// ---------------------------------------------------------------------------
extern "C" void kernel_launch(void* const* d_in, const int* in_sizes, int n_in,
                              void* d_out, int out_size) {
    const float* x     = (const float*)d_in[0];
    const int*   gmm   = (const int*)d_in[1];
    const float* w0    = (const float*)d_in[2];
    const float* w1    = (const float*)d_in[3];
    const float* gamma = (const float*)d_in[4];
    const float* beta  = (const float*)d_in[5];
    float* out = (float*)d_out;

    int E = in_sizes[0] / (B_ * CIN_);
    if (E <= 0 || E > EMAX_) E = EMAX_;

    const int SMEM = 4096 + 2 * 4 * 10240;   // 86016 B: idx + 2 buffers x 4 bf16 tiles
    cudaFuncSetAttribute(conv_m<CIN_, false>, cudaFuncAttributeMaxDynamicSharedMemorySize, SMEM);
    cudaFuncSetAttribute(conv_m<COUT_, true>, cudaFuncAttributeMaxDynamicSharedMemorySize, SMEM);

    dim3 tgrid((E + 31) / 32, CIN_ / 32, B_);
    transpose_k<<<tgrid, dim3(32, 8)>>>(x, E);

    int etiles = (E + 127) / 128;
    conv_m<CIN_, false><<<dim3(etiles, 2, B_), 256, SMEM>>>(gmm, w0, nullptr, E);
    scale_k<<<1, 256>>>(gamma, beta, E);
    conv_m<COUT_, true><<<dim3(etiles, 2, B_), 256, SMEM>>>(gmm, w1, out, E);
}

// round 11
// speedup vs baseline: 1.7823x; 1.0515x over previous
#include <cuda_runtime.h>
#include <cuda_bf16.h>
#include <cstdint>

typedef uint32_t u32;

#define B_    4
#define CIN_  128
#define COUT_ 256
#define EMAX_ 20000
#define EPSBN 1e-5f

// ---------------- device scratch (no runtime allocation) ----------------
__device__ float g_xt[(size_t)B_ * EMAX_ * CIN_];    // x transposed [b][e][c]
__device__ float g_yt[(size_t)B_ * EMAX_ * COUT_];   // conv0 out [b][e][o]
__device__ float g_sum[COUT_];
__device__ float g_sumsq[COUT_];
__device__ float g_a[COUT_];
__device__ float g_bsh[COUT_];

__device__ __forceinline__ u32 pkbf(__nv_bfloat16 a, __nv_bfloat16 b) {
    __nv_bfloat162 t;
    t.x = a; t.y = b;
    return *reinterpret_cast<u32*>(&t);
}

#define MMA_BF16(d, a0, a1, b0) \
    asm volatile("mma.sync.aligned.m16n8k8.row.col.f32.bf16.bf16.f32 " \
                 "{%0,%1,%2,%3}, {%4,%5}, {%6}, {%0,%1,%2,%3};" \
                 : "+f"((d)[0]), "+f"((d)[1]), "+f"((d)[2]), "+f"((d)[3]) \
                 : "r"(a0), "r"(a1), "r"(b0))

// ---------------------------------------------------------------------------
// Transpose x [B][CIN][E] -> g_xt [B][E][CIN]; block (0,0,0) zeroes BN stats.
// ---------------------------------------------------------------------------
__global__ void transpose_k(const float* __restrict__ x, int E) {
    __shared__ float tile[32][33];
    if (blockIdx.x == 0 && blockIdx.y == 0 && blockIdx.z == 0) {
        int t = threadIdx.y * 32 + threadIdx.x;
        g_sum[t] = 0.f;
        g_sumsq[t] = 0.f;
    }
    int b  = blockIdx.z;
    int c0 = blockIdx.y * 32;
    int e0 = blockIdx.x * 32;
    for (int r = threadIdx.y; r < 32; r += 8) {
        int c = c0 + r, e = e0 + threadIdx.x;
        tile[r][threadIdx.x] = (e < E) ? x[((size_t)b * CIN_ + c) * E + e] : 0.f;
    }
    __syncthreads();
    for (int r = threadIdx.y; r < 32; r += 8) {
        int e = e0 + r, c = c0 + threadIdx.x;
        if (e < E) g_xt[((size_t)b * E + e) * CIN_ + c] = tile[threadIdx.x][r];
    }
}

// ---------------------------------------------------------------------------
// Fused gather + symmetric funcs + bf16-split tensor-core GEMM (mma.sync),
// with software-pipelined gather: prefetch(cc+1) LDGs -> MMA(cc) -> commit(cc+1).
// Tile: M=128 (out ch) x N=128 (edges); K chunk = 8 ch * 5 = 40 bf16 values.
// D = Whi*Ghi + Whi*Glo + Wlo*Ghi  (fp32 accum; lo*lo term ~2^-18, dropped)
// Double-buffered, 2 CTAs/SM.
// ---------------------------------------------------------------------------
template <int CIN, bool PHASE2>
__global__ __launch_bounds__(256, 2) void conv_m(const int* __restrict__ gmm,
                                                 const float* __restrict__ w,
                                                 float* __restrict__ dout, int E) {
    constexpr int KC = 8;
    constexpr int KB = KC * 5;          // 40 k values per chunk
    constexpr int RW = KB / 2;          // 20 u32 words per bf16 row
    constexpr int TILE = 128 * RW;      // words per operand tile (10240 B)
    constexpr int TDS = 132;            // Td row stride (floats)

    extern __shared__ u32 sm32[];
    int* idxs  = (int*)sm32;            // [4][128]  (2048 B)
    u32* tiles = sm32 + 1024;           // buffers at byte 4096
    float* Td  = (float*)(sm32 + 1024); // epilogue overlay [128][TDS]

    const int tid = threadIdx.x;
    const int wid = tid >> 5;
    const int lane = tid & 31;
    const int gid = lane >> 2;
    const int t4  = lane & 3;
    const int e0 = blockIdx.x * 128;
    const int o0 = blockIdx.y * 128;
    const int b  = blockIdx.z;
    const float* srcb = (PHASE2 ? g_yt : g_xt) + (size_t)b * E * CIN;

    // warp tile: 32 (M) x 64 (N)
    const int m0 = (wid & 3) * 32;
    const int n0 = (wid >> 2) * 64;

    for (int i = tid; i < 512; i += 256) {
        int el = i >> 2, j = i & 3;
        int eg = e0 + el;
        idxs[j * 128 + el] = (eg < E) ? gmm[((size_t)b * E + eg) * 4 + j] : 0;
    }
    __syncthreads();

    const int ch  = tid & (KC - 1);
    const int elb = tid >> 3;

    // ---- issue the scattered gather loads for chunk cc into registers
    auto prefetch_g = [&](int cc, float gv[4][5]) {
        int c = cc * KC + ch;
#pragma unroll
        for (int p = 0; p < 4; p++) {
            int el = elb + p * 32;
            int eg = e0 + el;
            int si = (eg < E) ? eg : 0;
            gv[p][0] = srcb[(size_t)si * CIN + c];
#pragma unroll
            for (int j = 0; j < 4; j++)
                gv[p][j + 1] = srcb[(size_t)idxs[j * 128 + el] * CIN + c];
        }
    };

    // ---- convert + store chunk cc (weights loaded here; G regs from prefetch)
    auto commit = [&](int cc, int sb, float gv[4][5]) {
        u32* Wh = tiles + sb * 4 * TILE;
        u32* Wl = Wh + TILE;
        u32* Gh = Wh + 2 * TILE;
        u32* Gl = Wh + 3 * TILE;
        // issue weight loads first — latency hides behind the G conversions
        float4 wv[5];
#pragma unroll
        for (int q = 0; q < 5; q++) {
            int i = tid + q * 256;
            int o = i / 10, kq = i % 10;
            wv[q] = *(const float4*)(w + ((size_t)(o0 + o) * CIN + cc * KC) * 5 + kq * 4);
        }
        // G: BN affine (phase2) + symmetric functions -> bf16 hi/lo
        int c = cc * KC + ch;
        float ac = 0.f, bc = 0.f;
        if constexpr (PHASE2) { ac = g_a[c]; bc = g_bsh[c]; }
#pragma unroll
        for (int p = 0; p < 4; p++) {
            int el = elb + p * 32;
            float v0 = gv[p][0], v1 = gv[p][1], v2 = gv[p][2], v3 = gv[p][3], v4 = gv[p][4];
            if constexpr (PHASE2) {
                v0 = fmaf(ac, fmaxf(v0, 0.f), bc);
                v1 = fmaf(ac, fmaxf(v1, 0.f), bc);
                v2 = fmaf(ac, fmaxf(v2, 0.f), bc);
                v3 = fmaf(ac, fmaxf(v3, 0.f), bc);
                v4 = fmaf(ac, fmaxf(v4, 0.f), bc);
            }
            float f[5];
            f[0] = v0;
            f[1] = v1 + v3;
            f[2] = v2 + v4;
            f[3] = fabsf(v1 - v3);
            f[4] = fabsf(v2 - v4);
            __nv_bfloat16* gh = (__nv_bfloat16*)Gh + el * KB + ch * 5;
            __nv_bfloat16* gl = (__nv_bfloat16*)Gl + el * KB + ch * 5;
#pragma unroll
            for (int s = 0; s < 5; s++) {
                __nv_bfloat16 h = __float2bfloat16_rn(f[s]);
                gh[s] = h;
                gl[s] = __float2bfloat16_rn(f[s] - __bfloat162float(h));
            }
        }
        // W: hi/lo split -> smem
#pragma unroll
        for (int q = 0; q < 5; q++) {
            int i = tid + q * 256;
            int o = i / 10, kq = i % 10;
            float4 v = wv[q];
            __nv_bfloat16 hx = __float2bfloat16_rn(v.x);
            __nv_bfloat16 hy = __float2bfloat16_rn(v.y);
            __nv_bfloat16 hz = __float2bfloat16_rn(v.z);
            __nv_bfloat16 hw = __float2bfloat16_rn(v.w);
            __nv_bfloat16 lx = __float2bfloat16_rn(v.x - __bfloat162float(hx));
            __nv_bfloat16 ly = __float2bfloat16_rn(v.y - __bfloat162float(hy));
            __nv_bfloat16 lz = __float2bfloat16_rn(v.z - __bfloat162float(hz));
            __nv_bfloat16 lw = __float2bfloat16_rn(v.w - __bfloat162float(hw));
            int widx = o * RW + kq * 2;
            *(uint2*)(Wh + widx) = make_uint2(pkbf(hx, hy), pkbf(hz, hw));
            *(uint2*)(Wl + widx) = make_uint2(pkbf(lx, ly), pkbf(lz, lw));
        }
    };

    float acc[2][8][4];
#pragma unroll
    for (int mt = 0; mt < 2; mt++)
#pragma unroll
        for (int nt = 0; nt < 8; nt++)
#pragma unroll
            for (int cq = 0; cq < 4; cq++) acc[mt][nt][cq] = 0.f;

    const int nch = CIN / KC;
    {
        float gv0[4][5];
        prefetch_g(0, gv0);
        commit(0, 0, gv0);
    }

    for (int cc = 0; cc < nch; cc++) {
        __syncthreads();

        float gv[4][5];
        const bool havenext = (cc + 1 < nch);
        if (havenext) prefetch_g(cc + 1, gv);   // LDGs in flight across the MMA burst

        const u32* Wh = tiles + (cc & 1) * 4 * TILE;
        const u32* Wl = Wh + TILE;
        const u32* Gh = Wh + 2 * TILE;
        const u32* Gl = Wh + 3 * TILE;
#pragma unroll
        for (int ks = 0; ks < 5; ks++) {
            int kwd = ks * 4 + t4;
            u32 ah[2][2], al[2][2];
#pragma unroll
            for (int mt = 0; mt < 2; mt++) {
                int base = (m0 + mt * 16 + gid) * RW + kwd;
                ah[mt][0] = Wh[base];
                ah[mt][1] = Wh[base + 8 * RW];
                al[mt][0] = Wl[base];
                al[mt][1] = Wl[base + 8 * RW];
            }
#pragma unroll
            for (int nt = 0; nt < 8; nt++) {
                int bb = (n0 + nt * 8 + gid) * RW + kwd;
                u32 bh = Gh[bb];
                u32 bl = Gl[bb];
#pragma unroll
                for (int mt = 0; mt < 2; mt++) {
                    MMA_BF16(acc[mt][nt], ah[mt][0], ah[mt][1], bh);
                    MMA_BF16(acc[mt][nt], ah[mt][0], ah[mt][1], bl);
                    MMA_BF16(acc[mt][nt], al[mt][0], al[mt][1], bh);
                }
            }
        }

        if (havenext) commit(cc + 1, (cc + 1) & 1, gv);
    }

    // ---- epilogue: dump accumulators to Td[e][o] (overlays ring buffers)
    __syncthreads();
#pragma unroll
    for (int mt = 0; mt < 2; mt++)
#pragma unroll
        for (int nt = 0; nt < 8; nt++)
#pragma unroll
            for (int cq = 0; cq < 4; cq++) {
                int ol = m0 + mt * 16 + gid + (cq >> 1) * 8;
                int el = n0 + nt * 8 + t4 * 2 + (cq & 1);
                Td[el * TDS + ol] = acc[mt][nt][cq];
            }
    __syncthreads();

    if constexpr (!PHASE2) {
        // BN stats: thread owns channel o = tid&127 over half the e rows
        {
            int ol = tid & 127, h = tid >> 7;
            float s = 0.f, s2 = 0.f;
            for (int r = 0; r < 64; r++) {
                int el = h * 64 + r;
                if (e0 + el < E) {
                    float v = fmaxf(Td[el * TDS + ol], 0.f);
                    s += v;
                    s2 += v * v;
                }
            }
            atomicAdd(&g_sum[o0 + ol], s);
            atomicAdd(&g_sumsq[o0 + ol], s2);
        }
        // coalesced yt store (pre-relu)
        for (int i = tid; i < 128 * 32; i += 256) {
            int el = i >> 5, q = i & 31;
            int e = e0 + el;
            if (e < E)
                *(float4*)&g_yt[((size_t)b * E + e) * COUT_ + o0 + q * 4] =
                    *(float4*)&Td[el * TDS + q * 4];
        }
    } else {
        // residual + relu in Td (coalesced yt rows)
        for (int i = tid; i < 128 * 32; i += 256) {
            int el = i >> 5, q = i & 31;
            int e = e0 + el;
            if (e < E) {
                float4 r = *(const float4*)&g_yt[((size_t)b * E + e) * COUT_ + o0 + q * 4];
                float4 t = *(float4*)&Td[el * TDS + q * 4];
                t.x = fmaxf(t.x + r.x, 0.f);
                t.y = fmaxf(t.y + r.y, 0.f);
                t.z = fmaxf(t.z + r.z, 0.f);
                t.w = fmaxf(t.w + r.w, 0.f);
                *(float4*)&Td[el * TDS + q * 4] = t;
            }
        }
        __syncthreads();
        // transposed store out[b][o][e] (scalar, coalesced along e)
        for (int i = tid; i < 128 * 128; i += 256) {
            int el = i & 127, ol = i >> 7;
            int e = e0 + el;
            if (e < E)
                dout[((size_t)b * COUT_ + o0 + ol) * E + e] = Td[el * TDS + ol];
        }
    }
}

// ---------------------------------------------------------------------------
__global__ void scale_k(const float* __restrict__ gamma,
                        const float* __restrict__ beta, int E) {
    int c = threadIdx.x;
    float n = (float)(B_ * E);
    float mean = g_sum[c] / n;
    float var  = g_sumsq[c] / n - mean * mean;
    float a = gamma[c] * rsqrtf(var + EPSBN);
    g_a[c]   = a;
    g_bsh[c] = beta[c] - mean * a;
}

// ---------------------------------------------------------------------------
extern "C" void kernel_launch(void* const* d_in, const int* in_sizes, int n_in,
                              void* d_out, int out_size) {
    const float* x     = (const float*)d_in[0];
    const int*   gmm   = (const int*)d_in[1];
    const float* w0    = (const float*)d_in[2];
    const float* w1    = (const float*)d_in[3];
    const float* gamma = (const float*)d_in[4];
    const float* beta  = (const float*)d_in[5];
    float* out = (float*)d_out;

    int E = in_sizes[0] / (B_ * CIN_);
    if (E <= 0 || E > EMAX_) E = EMAX_;

    const int SMEM = 4096 + 2 * 4 * 10240;   // 86016 B: idx + 2 buffers x 4 bf16 tiles
    cudaFuncSetAttribute(conv_m<CIN_, false>, cudaFuncAttributeMaxDynamicSharedMemorySize, SMEM);
    cudaFuncSetAttribute(conv_m<COUT_, true>, cudaFuncAttributeMaxDynamicSharedMemorySize, SMEM);

    dim3 tgrid((E + 31) / 32, CIN_ / 32, B_);
    transpose_k<<<tgrid, dim3(32, 8)>>>(x, E);

    int etiles = (E + 127) / 128;
    conv_m<CIN_, false><<<dim3(etiles, 2, B_), 256, SMEM>>>(gmm, w0, nullptr, E);
    scale_k<<<1, 256>>>(gamma, beta, E);
    conv_m<COUT_, true><<<dim3(etiles, 2, B_), 256, SMEM>>>(gmm, w1, out, E);
}

// round 13
// speedup vs baseline: 2.2977x; 1.2891x over previous
#include <cuda_runtime.h>
#include <cuda_fp16.h>
#include <cstdint>

typedef uint32_t u32;

#define B_    4
#define CIN_  128
#define COUT_ 256
#define EMAX_ 20000
#define EPSBN 1e-5f

// ---------------- device scratch (no runtime allocation) ----------------
__device__ float g_xt[(size_t)B_ * EMAX_ * CIN_];    // x transposed [b][e][c]
__device__ float g_yt[(size_t)B_ * EMAX_ * COUT_];   // conv0 out [b][e][o]
__device__ float g_sum[COUT_];
__device__ float g_sumsq[COUT_];
__device__ float g_a[COUT_];
__device__ float g_bsh[COUT_];

__device__ __forceinline__ u32 pkhf(__half a, __half b) {
    __half2 t;
    t.x = a; t.y = b;
    return *reinterpret_cast<u32*>(&t);
}

#define MMA_F16(d, a0, a1, b0) \
    asm volatile("mma.sync.aligned.m16n8k8.row.col.f32.f16.f16.f32 " \
                 "{%0,%1,%2,%3}, {%4,%5}, {%6}, {%0,%1,%2,%3};" \
                 : "+f"((d)[0]), "+f"((d)[1]), "+f"((d)[2]), "+f"((d)[3]) \
                 : "r"(a0), "r"(a1), "r"(b0))

// ---------------------------------------------------------------------------
// Transpose x [B][CIN][E] -> g_xt [B][E][CIN]; block (0,0,0) zeroes BN stats.
// ---------------------------------------------------------------------------
__global__ void transpose_k(const float* __restrict__ x, int E) {
    __shared__ float tile[32][33];
    if (blockIdx.x == 0 && blockIdx.y == 0 && blockIdx.z == 0) {
        int t = threadIdx.y * 32 + threadIdx.x;
        g_sum[t] = 0.f;
        g_sumsq[t] = 0.f;
    }
    int b  = blockIdx.z;
    int c0 = blockIdx.y * 32;
    int e0 = blockIdx.x * 32;
    for (int r = threadIdx.y; r < 32; r += 8) {
        int c = c0 + r, e = e0 + threadIdx.x;
        tile[r][threadIdx.x] = (e < E) ? x[((size_t)b * CIN_ + c) * E + e] : 0.f;
    }
    __syncthreads();
    for (int r = threadIdx.y; r < 32; r += 8) {
        int e = e0 + r, c = c0 + threadIdx.x;
        if (e < E) g_xt[((size_t)b * E + e) * CIN_ + c] = tile[threadIdx.x][r];
    }
}

// ---------------------------------------------------------------------------
// Fused gather + symmetric funcs + fp16 2-term tensor-core GEMM (mma.sync),
// software-pipelined gather: prefetch(cc+1) LDGs -> MMA(cc) -> commit(cc+1).
// Tile: M=128 (out ch) x N=128 (edges); K chunk = 8 ch * 5 = 40 fp16 values.
// D = W*Ghi + W*Glo  (W single fp16, G split hi/lo; fp32 accum)
// Error ~2^-11 on W only -> norm rel err ~2-4e-4 (<1e-3 budget).
// Double-buffered, 2 CTAs/SM.
// ---------------------------------------------------------------------------
template <int CIN, bool PHASE2>
__global__ __launch_bounds__(256, 2) void conv_m(const int* __restrict__ gmm,
                                                 const float* __restrict__ w,
                                                 float* __restrict__ dout, int E) {
    constexpr int KC = 8;
    constexpr int KB = KC * 5;          // 40 k values per chunk
    constexpr int RW = KB / 2;          // 20 u32 words per fp16 row
    constexpr int TILE = 128 * RW;      // words per operand tile (10240 B)
    constexpr int TDS = 132;            // Td row stride (floats)

    extern __shared__ u32 sm32[];
    int* idxs  = (int*)sm32;            // [4][128]  (2048 B)
    u32* tiles = sm32 + 1024;           // buffers at byte 4096
    float* Td  = (float*)(sm32 + 1024); // epilogue overlay [128][TDS]

    const int tid = threadIdx.x;
    const int wid = tid >> 5;
    const int lane = tid & 31;
    const int gid = lane >> 2;
    const int t4  = lane & 3;
    const int e0 = blockIdx.x * 128;
    const int o0 = blockIdx.y * 128;
    const int b  = blockIdx.z;
    const float* srcb = (PHASE2 ? g_yt : g_xt) + (size_t)b * E * CIN;

    // warp tile: 32 (M) x 64 (N)
    const int m0 = (wid & 3) * 32;
    const int n0 = (wid >> 2) * 64;

    for (int i = tid; i < 512; i += 256) {
        int el = i >> 2, j = i & 3;
        int eg = e0 + el;
        idxs[j * 128 + el] = (eg < E) ? gmm[((size_t)b * E + eg) * 4 + j] : 0;
    }
    __syncthreads();

    const int ch  = tid & (KC - 1);
    const int elb = tid >> 3;

    // ---- issue the scattered gather loads for chunk cc into registers
    auto prefetch_g = [&](int cc, float gv[4][5]) {
        int c = cc * KC + ch;
#pragma unroll
        for (int p = 0; p < 4; p++) {
            int el = elb + p * 32;
            int eg = e0 + el;
            int si = (eg < E) ? eg : 0;
            gv[p][0] = srcb[(size_t)si * CIN + c];
#pragma unroll
            for (int j = 0; j < 4; j++)
                gv[p][j + 1] = srcb[(size_t)idxs[j * 128 + el] * CIN + c];
        }
    };

    // ---- convert + store chunk cc (weights loaded here; G regs from prefetch)
    auto commit = [&](int cc, int sb, float gv[4][5]) {
        u32* Wt = tiles + sb * 3 * TILE;
        u32* Gh = Wt + TILE;
        u32* Gl = Wt + 2 * TILE;
        // issue weight loads first — latency hides behind the G conversions
        float4 wv[5];
#pragma unroll
        for (int q = 0; q < 5; q++) {
            int i = tid + q * 256;
            int o = i / 10, kq = i % 10;
            wv[q] = *(const float4*)(w + ((size_t)(o0 + o) * CIN + cc * KC) * 5 + kq * 4);
        }
        // G: BN affine (phase2) + symmetric functions -> fp16 hi/lo
        int c = cc * KC + ch;
        float ac = 0.f, bc = 0.f;
        if constexpr (PHASE2) { ac = g_a[c]; bc = g_bsh[c]; }
#pragma unroll
        for (int p = 0; p < 4; p++) {
            int el = elb + p * 32;
            float v0 = gv[p][0], v1 = gv[p][1], v2 = gv[p][2], v3 = gv[p][3], v4 = gv[p][4];
            if constexpr (PHASE2) {
                v0 = fmaf(ac, fmaxf(v0, 0.f), bc);
                v1 = fmaf(ac, fmaxf(v1, 0.f), bc);
                v2 = fmaf(ac, fmaxf(v2, 0.f), bc);
                v3 = fmaf(ac, fmaxf(v3, 0.f), bc);
                v4 = fmaf(ac, fmaxf(v4, 0.f), bc);
            }
            float f[5];
            f[0] = v0;
            f[1] = v1 + v3;
            f[2] = v2 + v4;
            f[3] = fabsf(v1 - v3);
            f[4] = fabsf(v2 - v4);
            __half* gh = (__half*)Gh + el * KB + ch * 5;
            __half* gl = (__half*)Gl + el * KB + ch * 5;
#pragma unroll
            for (int s = 0; s < 5; s++) {
                __half h = __float2half_rn(f[s]);
                gh[s] = h;
                gl[s] = __float2half_rn(f[s] - __half2float(h));
            }
        }
        // W: single fp16 -> smem
#pragma unroll
        for (int q = 0; q < 5; q++) {
            int i = tid + q * 256;
            int o = i / 10, kq = i % 10;
            float4 v = wv[q];
            int widx = o * RW + kq * 2;
            *(uint2*)(Wt + widx) =
                make_uint2(pkhf(__float2half_rn(v.x), __float2half_rn(v.y)),
                           pkhf(__float2half_rn(v.z), __float2half_rn(v.w)));
        }
    };

    float acc[2][8][4];
#pragma unroll
    for (int mt = 0; mt < 2; mt++)
#pragma unroll
        for (int nt = 0; nt < 8; nt++)
#pragma unroll
            for (int cq = 0; cq < 4; cq++) acc[mt][nt][cq] = 0.f;

    const int nch = CIN / KC;
    {
        float gv0[4][5];
        prefetch_g(0, gv0);
        commit(0, 0, gv0);
    }

    for (int cc = 0; cc < nch; cc++) {
        __syncthreads();

        float gv[4][5];
        const bool havenext = (cc + 1 < nch);
        if (havenext) prefetch_g(cc + 1, gv);   // LDGs in flight across the MMA burst

        const u32* Wt = tiles + (cc & 1) * 3 * TILE;
        const u32* Gh = Wt + TILE;
        const u32* Gl = Wt + 2 * TILE;
#pragma unroll
        for (int ks = 0; ks < 5; ks++) {
            int kwd = ks * 4 + t4;
            u32 ah[2][2];
#pragma unroll
            for (int mt = 0; mt < 2; mt++) {
                int base = (m0 + mt * 16 + gid) * RW + kwd;
                ah[mt][0] = Wt[base];
                ah[mt][1] = Wt[base + 8 * RW];
            }
#pragma unroll
            for (int nt = 0; nt < 8; nt++) {
                int bb = (n0 + nt * 8 + gid) * RW + kwd;
                u32 bh = Gh[bb];
                u32 bl = Gl[bb];
#pragma unroll
                for (int mt = 0; mt < 2; mt++) {
                    MMA_F16(acc[mt][nt], ah[mt][0], ah[mt][1], bh);
                    MMA_F16(acc[mt][nt], ah[mt][0], ah[mt][1], bl);
                }
            }
        }

        if (havenext) commit(cc + 1, (cc + 1) & 1, gv);
    }

    // ---- epilogue: dump accumulators to Td[e][o] (overlays ring buffers)
    __syncthreads();
#pragma unroll
    for (int mt = 0; mt < 2; mt++)
#pragma unroll
        for (int nt = 0; nt < 8; nt++)
#pragma unroll
            for (int cq = 0; cq < 4; cq++) {
                int ol = m0 + mt * 16 + gid + (cq >> 1) * 8;
                int el = n0 + nt * 8 + t4 * 2 + (cq & 1);
                Td[el * TDS + ol] = acc[mt][nt][cq];
            }
    __syncthreads();

    if constexpr (!PHASE2) {
        // BN stats: thread owns channel o = tid&127 over half the e rows
        {
            int ol = tid & 127, h = tid >> 7;
            float s = 0.f, s2 = 0.f;
            for (int r = 0; r < 64; r++) {
                int el = h * 64 + r;
                if (e0 + el < E) {
                    float v = fmaxf(Td[el * TDS + ol], 0.f);
                    s += v;
                    s2 += v * v;
                }
            }
            atomicAdd(&g_sum[o0 + ol], s);
            atomicAdd(&g_sumsq[o0 + ol], s2);
        }
        // coalesced yt store (pre-relu)
        for (int i = tid; i < 128 * 32; i += 256) {
            int el = i >> 5, q = i & 31;
            int e = e0 + el;
            if (e < E)
                *(float4*)&g_yt[((size_t)b * E + e) * COUT_ + o0 + q * 4] =
                    *(float4*)&Td[el * TDS + q * 4];
        }
    } else {
        // residual + relu in Td (coalesced yt rows)
        for (int i = tid; i < 128 * 32; i += 256) {
            int el = i >> 5, q = i & 31;
            int e = e0 + el;
            if (e < E) {
                float4 r = *(const float4*)&g_yt[((size_t)b * E + e) * COUT_ + o0 + q * 4];
                float4 t = *(float4*)&Td[el * TDS + q * 4];
                t.x = fmaxf(t.x + r.x, 0.f);
                t.y = fmaxf(t.y + r.y, 0.f);
                t.z = fmaxf(t.z + r.z, 0.f);
                t.w = fmaxf(t.w + r.w, 0.f);
                *(float4*)&Td[el * TDS + q * 4] = t;
            }
        }
        __syncthreads();
        // transposed store out[b][o][e] (scalar, coalesced along e)
        for (int i = tid; i < 128 * 128; i += 256) {
            int el = i & 127, ol = i >> 7;
            int e = e0 + el;
            if (e < E)
                dout[((size_t)b * COUT_ + o0 + ol) * E + e] = Td[el * TDS + ol];
        }
    }
}

// ---------------------------------------------------------------------------
__global__ void scale_k(const float* __restrict__ gamma,
                        const float* __restrict__ beta, int E) {
    int c = threadIdx.x;
    float n = (float)(B_ * E);
    float mean = g_sum[c] / n;
    float var  = g_sumsq[c] / n - mean * mean;
    float a = gamma[c] * rsqrtf(var + EPSBN);
    g_a[c]   = a;
    g_bsh[c] = beta[c] - mean * a;
}

// ---------------------------------------------------------------------------
extern "C" void kernel_launch(void* const* d_in, const int* in_sizes, int n_in,
                              void* d_out, int out_size) {
    const float* x     = (const float*)d_in[0];
    const int*   gmm   = (const int*)d_in[1];
    const float* w0    = (const float*)d_in[2];
    const float* w1    = (const float*)d_in[3];
    const float* gamma = (const float*)d_in[4];
    const float* beta  = (const float*)d_in[5];
    float* out = (float*)d_out;

    int E = in_sizes[0] / (B_ * CIN_);
    if (E <= 0 || E > EMAX_) E = EMAX_;

    // smem: max(idx + 2 buffers x 3 fp16 tiles, epilogue overlay 128x132 f32)
    const int SMEM_RING = 4096 + 2 * 3 * 10240;          // 65536
    const int SMEM_EPI  = 4096 + 128 * 132 * 4;          // 71680
    const int SMEM = (SMEM_RING > SMEM_EPI) ? SMEM_RING : SMEM_EPI;
    cudaFuncSetAttribute(conv_m<CIN_, false>, cudaFuncAttributeMaxDynamicSharedMemorySize, SMEM);
    cudaFuncSetAttribute(conv_m<COUT_, true>, cudaFuncAttributeMaxDynamicSharedMemorySize, SMEM);

    dim3 tgrid((E + 31) / 32, CIN_ / 32, B_);
    transpose_k<<<tgrid, dim3(32, 8)>>>(x, E);

    int etiles = (E + 127) / 128;
    conv_m<CIN_, false><<<dim3(etiles, 2, B_), 256, SMEM>>>(gmm, w0, nullptr, E);
    scale_k<<<1, 256>>>(gamma, beta, E);
    conv_m<COUT_, true><<<dim3(etiles, 2, B_), 256, SMEM>>>(gmm, w1, out, E);
}